// round 2
// baseline (speedup 1.0000x reference)
#include <cuda_runtime.h>

// Fused: channel-mix (w1) -> double-unfold 1D conv along W (w0, with the
// torch-style two-stage zero-pad masks) -> roll(+1) along H.
//
// x  : [128, 56, 56] f32   (d_in[0])
// w0 : [32, 2, 3, 3] f32   (d_in[1])
// w1 : [4, 64]       f32   (d_in[2])
// out: [128, 56, 56] f32
//
// out[l*4+p, o, n] = sum_{j,i,k} w0[l,j,i,k] * t4[p,j,(o-1)%56, n+i+k-2]
//                    * [0 <= n+k-1 < 56] * [0 <= n+i+k-2 < 56]
// t4[p,j,h,w] = sum_c w1[p,c] * x[2c+j, h, w]
//
// Grouped by d=i+k the masks are uniform per d except d=2, giving a 7-term
// combined-weight kernel per (channel, j):
//   r0 = w(0,0)           mask n>=2   (pairs with t4[n-2])
//   r1 = w(0,1)+w(1,0)    mask n>=1   (t4[n-1])
//   r2 = w(1,1)           always      (t4[n])
//   r3 = w(2,0)           mask n>=1   (t4[n])
//   r4 = w(0,2)           mask n<=54  (t4[n])
//   r5 = w(1,2)+w(2,1)    mask n<=54  (t4[n+1])
//   r6 = w(2,2)           mask n<=53  (t4[n+2])

#define NT 448

__global__ __launch_bounds__(NT, 1) void fused_shuffleconv(
    const float* __restrict__ x,
    const float* __restrict__ w0,
    const float* __restrict__ w1,
    float* __restrict__ out)
{
    __shared__ float xs[128 * 56];     // source x row  (28672 B)
    __shared__ float t4s[8 * 56];      // t4[(p*2+j)][w]
    __shared__ float w1s[4 * 64];
    __shared__ float wcs[32 * 16];     // combined weights: [l][j*7+r], padded to 16

    const int tid  = threadIdx.x;
    const int o    = blockIdx.x;
    const int hsrc = (o + 55) % 56;    // roll(+1): out row o uses y row o-1

    // ---- prologue: weights + x row into smem (independent loads) ----
    if (tid < 256) w1s[tid] = w1[tid];

    {   // 448 threads -> exactly 32*14 combined-weight entries
        int l = tid / 14, q = tid % 14;
        int j = q / 7,    r = q % 7;
        const float* wb = w0 + (l * 2 + j) * 9;   // [3][3] block, idx = i*3+k
        float v;
        switch (r) {
            case 0:  v = wb[0];          break;   // (0,0)
            case 1:  v = wb[1] + wb[3];  break;   // (0,1)+(1,0)
            case 2:  v = wb[4];          break;   // (1,1)
            case 3:  v = wb[6];          break;   // (2,0)
            case 4:  v = wb[2];          break;   // (0,2)
            case 5:  v = wb[5] + wb[7];  break;   // (1,2)+(2,1)
            default: v = wb[8];          break;   // (2,2)
        }
        wcs[l * 16 + j * 7 + r] = v;
    }

    // x row: 128 channels x 56 floats = 1792 float4 (rows are 16B aligned)
    #pragma unroll
    for (int g = tid; g < 128 * 14; g += NT) {
        int c = g / 14, q = g % 14;
        float4 v = *(const float4*)(x + c * 3136 + hsrc * 56 + q * 4);
        *(float4*)(xs + c * 56 + q * 4) = v;
    }
    __syncthreads();

    const int n  = tid % 56;
    const int sg = tid / 56;           // 0..7: stage1 (p,j) group / stage2 channel group

    // ---- stage 1: t4s[(p*2+j)][n] = sum_c w1[p,c] * xs[2c+j][n] ----
    {
        int p = sg >> 1, j = sg & 1;
        const float4* wv = (const float4*)(w1s + p * 64);
        const float*  xb = xs + j * 56 + n;
        float acc = 0.f;
        #pragma unroll
        for (int c4 = 0; c4 < 16; c4++) {
            float4 w4 = wv[c4];
            int c = c4 * 8;            // 2*c element stride = 112 floats per c
            acc = fmaf(w4.x, xb[(c    ) * 56], acc);
            acc = fmaf(w4.y, xb[(c + 2) * 56], acc);
            acc = fmaf(w4.z, xb[(c + 4) * 56], acc);
            acc = fmaf(w4.w, xb[(c + 6) * 56], acc);
        }
        t4s[sg * 56 + n] = acc;
    }
    __syncthreads();

    // ---- stage 2: each thread = one n, fixed p, 16 channels ----
    const int p     = sg & 3;
    const int lbase = (sg >> 2) * 16;

    // masked t4 neighborhood (clamped indices keep loads in-bounds; masks zero them)
    const int im2 = n >= 2 ? n - 2 : 0;
    const int im1 = n >= 1 ? n - 1 : 0;
    const int ip1 = n <= 54 ? n + 1 : 55;
    const int ip2 = n <= 53 ? n + 2 : 55;

    float va[2], vb[2], vc[2], vc1[2], vc2[2], vd[2], ve[2];
    #pragma unroll
    for (int j = 0; j < 2; j++) {
        const float* tb = t4s + (p * 2 + j) * 56;
        float c = tb[n];
        va[j]  = (n >= 2)  ? tb[im2] : 0.f;
        vb[j]  = (n >= 1)  ? tb[im1] : 0.f;
        vc[j]  = c;
        vc1[j] = (n >= 1)  ? c       : 0.f;
        vc2[j] = (n <= 54) ? c       : 0.f;
        vd[j]  = (n <= 54) ? tb[ip1] : 0.f;
        ve[j]  = (n <= 53) ? tb[ip2] : 0.f;
    }

    float* ob = out + o * 56 + n;
    #pragma unroll
    for (int m = 0; m < 16; m++) {
        int l = lbase + m;
        const float4* wp = (const float4*)(wcs + l * 16);
        float4 A = wp[0];   // j0: r0 r1 r2 r3
        float4 B = wp[1];   // j0: r4 r5 r6 | j1: r0
        float4 C = wp[2];   // j1: r1 r2 r3 r4
        float4 D = wp[3];   // j1: r5 r6 pad pad
        float acc;
        acc  = A.x * va[0]  + A.y * vb[0]  + A.z * vc[0]  + A.w * vc1[0];
        acc += B.x * vc2[0] + B.y * vd[0]  + B.z * ve[0];
        acc += B.w * va[1]  + C.x * vb[1]  + C.y * vc[1]  + C.z * vc1[1];
        acc += C.w * vc2[1] + D.x * vd[1]  + D.y * ve[1];
        ob[(l * 4 + p) * 3136] = acc;
    }
}

extern "C" void kernel_launch(void* const* d_in, const int* in_sizes, int n_in,
                              void* d_out, int out_size) {
    const float* x  = (const float*)d_in[0];
    const float* w0 = (const float*)d_in[1];
    const float* w1 = (const float*)d_in[2];
    float* out = (float*)d_out;
    fused_shuffleconv<<<56, NT>>>(x, w0, w1, out);
}